// round 2
// baseline (speedup 1.0000x reference)
#include <cuda_runtime.h>
#include <math.h>

#define BB 2
#define NN 2048
#define DD 1024
#define HH 16
#define HD 64

// -------- scratch (static device arrays; no allocation) --------
__device__ float g_q[(size_t)BB*HH*NN*HD];
__device__ float g_k[(size_t)BB*HH*NN*HD];
__device__ float g_v[(size_t)BB*HH*NN*HD];
__device__ float g_ctx[(size_t)BB*NN*DD];

// ============================================================
// GEMM: C = A[M,K] * W[N,K]^T (+bias).  M=4096, N=1024, K=1024.
// mode 0: scatter into head layout [(b*H+h)*NN + i]*HD + c  (for Q/K/V)
// mode 1: row-major C[m*DD+n] + bias  (final projection)
// 64x64 block tile, 256 threads, 4x4 per-thread micro tile, BK=16.
// ============================================================
__global__ __launch_bounds__(256) void gemm_nt_kernel(
    const float* __restrict__ A, const float* __restrict__ W,
    const float* __restrict__ bias, float* __restrict__ C, int mode)
{
    __shared__ float As[16*68];
    __shared__ float Bs[16*68];

    const int tid = threadIdx.x;
    const int m0 = blockIdx.y * 64;
    const int n0 = blockIdx.x * 64;
    const int lr = tid >> 2;          // 0..63 row within tile
    const int ls = (tid & 3) * 4;     // k offset 0,4,8,12
    const int ty = tid >> 4;          // 0..15
    const int tx = tid & 15;          // 0..15

    float acc[4][4];
#pragma unroll
    for (int u = 0; u < 4; u++)
#pragma unroll
        for (int v = 0; v < 4; v++) acc[u][v] = 0.f;

    for (int k0 = 0; k0 < DD; k0 += 16) {
        float4 av = *(const float4*)&A[(size_t)(m0 + lr) * DD + k0 + ls];
        float4 bv = *(const float4*)&W[(size_t)(n0 + lr) * DD + k0 + ls];
        As[(ls + 0) * 68 + lr] = av.x;
        As[(ls + 1) * 68 + lr] = av.y;
        As[(ls + 2) * 68 + lr] = av.z;
        As[(ls + 3) * 68 + lr] = av.w;
        Bs[(ls + 0) * 68 + lr] = bv.x;
        Bs[(ls + 1) * 68 + lr] = bv.y;
        Bs[(ls + 2) * 68 + lr] = bv.z;
        Bs[(ls + 3) * 68 + lr] = bv.w;
        __syncthreads();
#pragma unroll
        for (int kk = 0; kk < 16; kk++) {
            float4 a = *(const float4*)&As[kk * 68 + ty * 4];
            float4 b = *(const float4*)&Bs[kk * 68 + tx * 4];
            float ar[4] = {a.x, a.y, a.z, a.w};
            float br[4] = {b.x, b.y, b.z, b.w};
#pragma unroll
            for (int u = 0; u < 4; u++)
#pragma unroll
                for (int v = 0; v < 4; v++) acc[u][v] += ar[u] * br[v];
        }
        __syncthreads();
    }

    if (mode == 0) {
        // scatter into [B,H,N,HD]
#pragma unroll
        for (int u = 0; u < 4; u++) {
            int m = m0 + ty * 4 + u;
            int b = m >> 11;          // /NN
            int i = m & (NN - 1);
#pragma unroll
            for (int v = 0; v < 4; v++) {
                int n = n0 + tx * 4 + v;
                int h = n >> 6;
                int c = n & 63;
                C[((size_t)(b * HH + h) * NN + i) * HD + c] = acc[u][v];
            }
        }
    } else {
#pragma unroll
        for (int u = 0; u < 4; u++) {
            int m = m0 + ty * 4 + u;
            float4 o;
            int n = n0 + tx * 4;
            o.x = acc[u][0] + bias[n + 0];
            o.y = acc[u][1] + bias[n + 1];
            o.z = acc[u][2] + bias[n + 2];
            o.w = acc[u][3] + bias[n + 3];
            *(float4*)&C[(size_t)m * DD + n] = o;
        }
    }
}

// ============================================================
// Attention with adaptive-temperature softmax.
// Grid (N/64, H, B), 256 threads. Two passes over causal key tiles.
// ============================================================
__device__ __forceinline__ float warpMax(float v) {
#pragma unroll
    for (int o = 16; o > 0; o >>= 1) v = fmaxf(v, __shfl_xor_sync(0xffffffffu, v, o));
    return v;
}
__device__ __forceinline__ float warpSum(float v) {
#pragma unroll
    for (int o = 16; o > 0; o >>= 1) v += __shfl_xor_sync(0xffffffffu, v, o);
    return v;
}

#define ST 68  // padded row stride for 64-wide tiles
#define MASKV (-1e30f)

__device__ __forceinline__ void load_tile64(float* dst, const float* __restrict__ src, int tid) {
    // src: row-major 64x64 contiguous; dst: stride ST
    int r = tid >> 2;
    int s4 = (tid & 3) * 16;
    const float4* s = (const float4*)(src + (size_t)r * 64 + s4);
    float4* d = (float4*)(dst + r * ST + s4);
    d[0] = s[0]; d[1] = s[1]; d[2] = s[2]; d[3] = s[3];
}

__global__ __launch_bounds__(256) void attn_kernel(float* __restrict__ gO)
{
    extern __shared__ float sm[];
    float* sQ = sm;                 // 64*ST
    float* sK = sQ + 64 * ST;
    float* sV = sK + 64 * ST;
    float* sS = sV + 64 * ST;       // scores / probs
    float* sBeta = sS + 64 * ST;    // 64
    float* sMp   = sBeta + 64;      // 64 (beta*m)
    float* sL    = sMp + 64;        // 64 (l')

    const int qt = blockIdx.x;
    const int h  = blockIdx.y;
    const int b  = blockIdx.z;
    const int tid = threadIdx.x;
    const int ty = tid >> 4, tx = tid & 15;
    const int w = tid >> 5, lane = tid & 31;
    const int i0 = ty * 4, j0 = tx * 4;
    const int q0 = qt * 64;

    const size_t headoff = (size_t)(b * HH + h) * NN * HD;
    const float* Qh = g_q + headoff;
    const float* Kh = g_k + headoff;
    const float* Vh = g_v + headoff;

    load_tile64(sQ, Qh + (size_t)q0 * HD, tid);

    // ---------- pass A: m, l, t(=sum e*s) per row ----------
    float mrow[8], lrow[8], trow[8];
#pragma unroll
    for (int rr = 0; rr < 8; rr++) { mrow[rr] = MASKV; lrow[rr] = 0.f; trow[rr] = 0.f; }

    for (int kt = 0; kt <= qt; kt++) {
        __syncthreads();
        load_tile64(sK, Kh + (size_t)kt * 64 * HD, tid);
        __syncthreads();

        float acc[4][4];
#pragma unroll
        for (int u = 0; u < 4; u++)
#pragma unroll
            for (int v = 0; v < 4; v++) acc[u][v] = 0.f;
#pragma unroll
        for (int d = 0; d < 64; d += 4) {
            float4 av[4], bv[4];
#pragma unroll
            for (int u = 0; u < 4; u++) av[u] = *(const float4*)&sQ[(i0 + u) * ST + d];
#pragma unroll
            for (int v = 0; v < 4; v++) bv[v] = *(const float4*)&sK[(j0 + v) * ST + d];
#pragma unroll
            for (int u = 0; u < 4; u++)
#pragma unroll
                for (int v = 0; v < 4; v++)
                    acc[u][v] += av[u].x * bv[v].x + av[u].y * bv[v].y
                               + av[u].z * bv[v].z + av[u].w * bv[v].w;
        }
#pragma unroll
        for (int u = 0; u < 4; u++) {
            int ig = q0 + i0 + u;
#pragma unroll
            for (int v = 0; v < 4; v++) {
                int jg = kt * 64 + j0 + v;
                float s = acc[u][v] * 0.125f;   // 1/sqrt(64)
                if (jg > ig) s = MASKV;
                sS[(i0 + u) * ST + j0 + v] = s;
            }
        }
        __syncthreads();

        // per-row online update (warp w owns rows w*8..w*8+7)
#pragma unroll
        for (int rr = 0; rr < 8; rr++) {
            int r = w * 8 + rr;
            float x1 = sS[r * ST + lane];
            float x2 = sS[r * ST + 32 + lane];
            float mt = warpMax(fmaxf(x1, x2));
            float mnew = fmaxf(mrow[rr], mt);
            float e1 = expf(x1 - mnew);
            float e2 = expf(x2 - mnew);
            float se = warpSum(e1 + e2);
            float st = warpSum(e1 * x1 + e2 * x2);
            float corr = expf(mrow[rr] - mnew);
            lrow[rr] = lrow[rr] * corr + se;
            trow[rr] = trow[rr] * corr + st;
            mrow[rr] = mnew;
        }
    }

    // entropy -> beta per row
#pragma unroll
    for (int rr = 0; rr < 8; rr++) {
        int r = w * 8 + rr;
        float l = lrow[rr], m = mrow[rr], t = trow[rr];
        float ent = logf(l) + m - t / l;
        float beta = 1.f;
        if (ent > 0.5f) {
            float poly = ((((-0.037f * ent + 0.481f) * ent - 2.3f) * ent + 4.917f) * ent - 1.791f);
            beta = fmaxf(poly, 1.f);
        }
        if (lane == 0) { sBeta[r] = beta; sMp[r] = beta * m; }
    }
    __syncthreads();

    float betas[4], mps[4];
#pragma unroll
    for (int u = 0; u < 4; u++) { betas[u] = sBeta[i0 + u]; mps[u] = sMp[i0 + u]; }

    // ---------- pass B: p = exp(beta*s - beta*m), O = P*V, l' ----------
    float O[4][4];
#pragma unroll
    for (int u = 0; u < 4; u++)
#pragma unroll
        for (int v = 0; v < 4; v++) O[u][v] = 0.f;
    float l2[8];
#pragma unroll
    for (int rr = 0; rr < 8; rr++) l2[rr] = 0.f;

    for (int kt = 0; kt <= qt; kt++) {
        __syncthreads();
        load_tile64(sK, Kh + (size_t)kt * 64 * HD, tid);
        load_tile64(sV, Vh + (size_t)kt * 64 * HD, tid);
        __syncthreads();

        float acc[4][4];
#pragma unroll
        for (int u = 0; u < 4; u++)
#pragma unroll
            for (int v = 0; v < 4; v++) acc[u][v] = 0.f;
#pragma unroll
        for (int d = 0; d < 64; d += 4) {
            float4 av[4], bv[4];
#pragma unroll
            for (int u = 0; u < 4; u++) av[u] = *(const float4*)&sQ[(i0 + u) * ST + d];
#pragma unroll
            for (int v = 0; v < 4; v++) bv[v] = *(const float4*)&sK[(j0 + v) * ST + d];
#pragma unroll
            for (int u = 0; u < 4; u++)
#pragma unroll
                for (int v = 0; v < 4; v++)
                    acc[u][v] += av[u].x * bv[v].x + av[u].y * bv[v].y
                               + av[u].z * bv[v].z + av[u].w * bv[v].w;
        }
#pragma unroll
        for (int u = 0; u < 4; u++) {
            int ig = q0 + i0 + u;
#pragma unroll
            for (int v = 0; v < 4; v++) {
                int jg = kt * 64 + j0 + v;
                float s = acc[u][v] * 0.125f;
                if (jg > ig) s = MASKV;
                float p = expf(betas[u] * s - mps[u]);
                sS[(i0 + u) * ST + j0 + v] = p;
            }
        }
        __syncthreads();

        // row sums of P
#pragma unroll
        for (int rr = 0; rr < 8; rr++) {
            int r = w * 8 + rr;
            l2[rr] += warpSum(sS[r * ST + lane] + sS[r * ST + 32 + lane]);
        }
        // O += P * V
#pragma unroll 4
        for (int j = 0; j < 64; j++) {
            float4 vv = *(const float4*)&sV[j * ST + j0];
            float pv[4];
#pragma unroll
            for (int u = 0; u < 4; u++) pv[u] = sS[(i0 + u) * ST + j];
#pragma unroll
            for (int u = 0; u < 4; u++) {
                O[u][0] += pv[u] * vv.x;
                O[u][1] += pv[u] * vv.y;
                O[u][2] += pv[u] * vv.z;
                O[u][3] += pv[u] * vv.w;
            }
        }
    }

#pragma unroll
    for (int rr = 0; rr < 8; rr++)
        if (lane == 0) sL[w * 8 + rr] = l2[rr];
    __syncthreads();

    // write ctx[b, q0+i, h*64 + d]
#pragma unroll
    for (int u = 0; u < 4; u++) {
        float inv = 1.f / sL[i0 + u];
        float4 o;
        o.x = O[u][0] * inv; o.y = O[u][1] * inv;
        o.z = O[u][2] * inv; o.w = O[u][3] * inv;
        size_t row = (size_t)(b * NN + q0 + i0 + u) * DD + h * HD + j0;
        *(float4*)&gO[row] = o;
    }
}

// ============================================================
extern "C" void kernel_launch(void* const* d_in, const int* in_sizes, int n_in,
                              void* d_out, int out_size)
{
    const float* x  = (const float*)d_in[0];
    const float* Wq = (const float*)d_in[1];
    const float* Wk = (const float*)d_in[2];
    const float* Wv = (const float*)d_in[3];
    const float* Wo = (const float*)d_in[4];
    const float* bo = (const float*)d_in[5];
    float* out = (float*)d_out;

    float *qp, *kp, *vp, *ctxp;
    cudaGetSymbolAddress((void**)&qp,   g_q);
    cudaGetSymbolAddress((void**)&kp,   g_k);
    cudaGetSymbolAddress((void**)&vp,   g_v);
    cudaGetSymbolAddress((void**)&ctxp, g_ctx);

    const int smem = (4 * 64 * ST + 3 * 64) * (int)sizeof(float);  // 70400 B
    cudaFuncSetAttribute(attn_kernel, cudaFuncAttributeMaxDynamicSharedMemorySize, smem);

    dim3 ggrid(DD / 64, (BB * NN) / 64);   // (16, 64)
    gemm_nt_kernel<<<ggrid, 256>>>(x, Wq, nullptr, qp, 0);
    gemm_nt_kernel<<<ggrid, 256>>>(x, Wk, nullptr, kp, 0);
    gemm_nt_kernel<<<ggrid, 256>>>(x, Wv, nullptr, vp, 0);

    dim3 agrid(NN / 64, HH, BB);           // (32, 16, 2)
    attn_kernel<<<agrid, 256, smem>>>(ctxp);

    gemm_nt_kernel<<<ggrid, 256>>>(ctxp, Wo, bo, out, 1);
}

// round 4
// speedup vs baseline: 1.7609x; 1.7609x over previous
#include <cuda_runtime.h>
#include <cstdint>
#include <math.h>

#define BB 2
#define NN 2048
#define DD 1024
#define HH 16
#define HD 64

__device__ float g_q[(size_t)BB*HH*NN*HD];
__device__ float g_k[(size_t)BB*HH*NN*HD];
__device__ float g_v[(size_t)BB*HH*NN*HD];
__device__ float g_ctx[(size_t)BB*NN*DD];

__device__ __forceinline__ float tf32r(float x){
    uint32_t r; asm("cvt.rna.tf32.f32 %0, %1;" : "=r"(r) : "f"(x));
    return __uint_as_float(r);
}
__device__ __forceinline__ float2 tsplit(float x){
    float h = tf32r(x);
    return make_float2(h, tf32r(x - h));
}
__device__ __forceinline__ void mma1(float4& d, uint32_t a0, uint32_t a1, uint32_t a2, uint32_t a3,
                                     uint32_t b0, uint32_t b1){
    asm volatile("mma.sync.aligned.m16n8k8.row.col.f32.tf32.tf32.f32 "
        "{%0,%1,%2,%3},{%4,%5,%6,%7},{%8,%9},{%0,%1,%2,%3};"
        : "+f"(d.x), "+f"(d.y), "+f"(d.z), "+f"(d.w)
        : "r"(a0), "r"(a1), "r"(a2), "r"(a3), "r"(b0), "r"(b1));
}
#define FU __float_as_uint
// 3xTF32: hi*hi + hi*lo + lo*hi
__device__ __forceinline__ void mma3(float4& d, const float2* a, const float2* b){
    mma1(d, FU(a[0].x), FU(a[1].x), FU(a[2].x), FU(a[3].x), FU(b[0].x), FU(b[1].x));
    mma1(d, FU(a[0].x), FU(a[1].x), FU(a[2].x), FU(a[3].x), FU(b[0].y), FU(b[1].y));
    mma1(d, FU(a[0].y), FU(a[1].y), FU(a[2].y), FU(a[3].y), FU(b[0].x), FU(b[1].x));
}

// ============================================================
// GEMM C = A[4096,1024] * W[1024,1024]^T (+bias). 128x128 tile, BK=32.
// 256 thr, 8 warps (4M x 2N), warp = 32x64, 3xTF32.
// ============================================================
#define GST 36  // float2 stride

__global__ __launch_bounds__(256, 2) void gemm_mma(
    const float* __restrict__ A, const float* __restrict__ W,
    const float* __restrict__ bias, float* __restrict__ C, int mode)
{
    extern __shared__ float2 gsm[];
    float2* As = gsm;                // 128*GST
    float2* Bs = gsm + 128 * GST;

    const int tid = threadIdx.x, lane = tid & 31, wid = tid >> 5;
    const int g = lane >> 2, t = lane & 3;
    const int wm = wid >> 1, wn = wid & 1;
    const int m0 = blockIdx.y * 128, n0 = blockIdx.x * 128;

    float4 acc[2][8];
#pragma unroll
    for (int i = 0; i < 2; i++)
#pragma unroll
        for (int j = 0; j < 8; j++) acc[i][j] = make_float4(0.f, 0.f, 0.f, 0.f);

    for (int k0 = 0; k0 < DD; k0 += 32) {
        float4 va[4], vb[4];
#pragma unroll
        for (int i = 0; i < 4; i++) {
            int idx = tid + i * 256, r = idx >> 3, c4 = idx & 7;
            va[i] = *(const float4*)&A[(size_t)(m0 + r) * DD + k0 + c4 * 4];
            vb[i] = *(const float4*)&W[(size_t)(n0 + r) * DD + k0 + c4 * 4];
        }
        __syncthreads();
#pragma unroll
        for (int i = 0; i < 4; i++) {
            int idx = tid + i * 256, r = idx >> 3, c4 = idx & 7;
            float2* pa = &As[r * GST + c4 * 4];
            float2* pb = &Bs[r * GST + c4 * 4];
            pa[0] = tsplit(va[i].x); pa[1] = tsplit(va[i].y);
            pa[2] = tsplit(va[i].z); pa[3] = tsplit(va[i].w);
            pb[0] = tsplit(vb[i].x); pb[1] = tsplit(vb[i].y);
            pb[2] = tsplit(vb[i].z); pb[3] = tsplit(vb[i].w);
        }
        __syncthreads();
#pragma unroll
        for (int kk = 0; kk < 4; kk++) {
            float2 af[2][4];
#pragma unroll
            for (int mt = 0; mt < 2; mt++) {
                int rb = wm * 32 + mt * 16;
                af[mt][0] = As[(rb + g)     * GST + kk * 8 + t];
                af[mt][1] = As[(rb + g + 8) * GST + kk * 8 + t];
                af[mt][2] = As[(rb + g)     * GST + kk * 8 + t + 4];
                af[mt][3] = As[(rb + g + 8) * GST + kk * 8 + t + 4];
            }
#pragma unroll
            for (int nt = 0; nt < 8; nt++) {
                int nr = wn * 64 + nt * 8 + g;
                float2 bf[2];
                bf[0] = Bs[nr * GST + kk * 8 + t];
                bf[1] = Bs[nr * GST + kk * 8 + t + 4];
                mma3(acc[0][nt], af[0], bf);
                mma3(acc[1][nt], af[1], bf);
            }
        }
        __syncthreads();
    }

#pragma unroll
    for (int mt = 0; mt < 2; mt++) {
        int r0 = m0 + wm * 32 + mt * 16 + g;
#pragma unroll
        for (int nt = 0; nt < 8; nt++) {
            int n = n0 + wn * 64 + nt * 8 + 2 * t;
            float4 c = acc[mt][nt];
            if (mode == 0) {
                int h = n >> 6, cc = n & 63;
                int b0r = r0 >> 11, i0r = r0 & (NN - 1);
                int b1r = (r0 + 8) >> 11, i1r = (r0 + 8) & (NN - 1);
                *(float2*)&C[((size_t)(b0r * HH + h) * NN + i0r) * HD + cc] = make_float2(c.x, c.y);
                *(float2*)&C[((size_t)(b1r * HH + h) * NN + i1r) * HD + cc] = make_float2(c.z, c.w);
            } else {
                float bx = bias[n], by = bias[n + 1];
                *(float2*)&C[(size_t)r0 * DD + n]       = make_float2(c.x + bx, c.y + by);
                *(float2*)&C[(size_t)(r0 + 8) * DD + n] = make_float2(c.z + bx, c.w + by);
            }
        }
    }
}

// ============================================================
// Attention: 256 thr, 8 warps x 16 q-rows, q-tile 128, key-tile 64.
// Two passes; adaptive-temperature softmax; 3xTF32 everywhere.
// ============================================================
#define AST 68  // float2 stride (64 + 4 pad)

__global__ __launch_bounds__(256, 1) void attn_mma(float* __restrict__ gctx)
{
    extern __shared__ float2 asm_[];
    float2* Qs = asm_;               // 128*AST
    float2* Ks = Qs + 128 * AST;     // 64*AST
    float2* Vs = Ks + 64 * AST;      // 64*AST
    float2* Ps = Vs + 64 * AST;      // 128*AST

    const int tid = threadIdx.x, lane = tid & 31, wid = tid >> 5;
    const int g = lane >> 2, t = lane & 3;
    const int qt = 15 - blockIdx.x;  // big tiles first
    const int h = blockIdx.y, b = blockIdx.z;
    const int q0 = qt * 128, ktmax = 2 * qt + 1;
    const size_t ho = (size_t)(b * HH + h) * NN * HD;
    const float *Q = g_q + ho, *K = g_k + ho, *V = g_v + ho;

    const int wr = wid * 16;             // warp row base in tile
    const int gr0 = q0 + wr + g, gr1 = gr0 + 8;

    // load Q tile
#pragma unroll
    for (int i = 0; i < 8; i++) {
        int idx = tid + i * 256, r = idx >> 4, c4 = idx & 15;
        float4 v = *(const float4*)&Q[(size_t)(q0 + r) * HD + c4 * 4];
        float2* p = &Qs[r * AST + c4 * 4];
        p[0] = tsplit(v.x); p[1] = tsplit(v.y); p[2] = tsplit(v.z); p[3] = tsplit(v.w);
    }

    float mr[2] = {-1e30f, -1e30f}, lr[2] = {0.f, 0.f}, tr[2] = {0.f, 0.f};

    // ================= pass A =================
    for (int kt = 0; kt <= ktmax; kt++) {
        int ktb = kt * 64;
        __syncthreads();
#pragma unroll
        for (int i = 0; i < 4; i++) {
            int idx = tid + i * 256, r = idx >> 4, c4 = idx & 15;
            float4 v = *(const float4*)&K[(size_t)(ktb + r) * HD + c4 * 4];
            float2* p = &Ks[r * AST + c4 * 4];
            p[0] = tsplit(v.x); p[1] = tsplit(v.y); p[2] = tsplit(v.z); p[3] = tsplit(v.w);
        }
        __syncthreads();
        if (ktb > q0 + wr + 15) continue;   // warp fully masked

        float4 s[8];
#pragma unroll
        for (int nt = 0; nt < 8; nt++) s[nt] = make_float4(0.f, 0.f, 0.f, 0.f);
#pragma unroll
        for (int kk = 0; kk < 8; kk++) {
            float2 af[4];
            af[0] = Qs[(wr + g)     * AST + kk * 8 + t];
            af[1] = Qs[(wr + g + 8) * AST + kk * 8 + t];
            af[2] = Qs[(wr + g)     * AST + kk * 8 + t + 4];
            af[3] = Qs[(wr + g + 8) * AST + kk * 8 + t + 4];
#pragma unroll
            for (int nt = 0; nt < 8; nt++) {
                float2 bf[2];
                bf[0] = Ks[(nt * 8 + g) * AST + kk * 8 + t];
                bf[1] = Ks[(nt * 8 + g) * AST + kk * 8 + t + 4];
                mma3(s[nt], af, bf);
            }
        }
#pragma unroll
        for (int rr = 0; rr < 2; rr++) {
            int gr = rr ? gr1 : gr0;
            float sv[16], cm = -1e30f;
#pragma unroll
            for (int nt = 0; nt < 8; nt++) {
                float x0 = rr ? s[nt].z : s[nt].x;
                float x1 = rr ? s[nt].w : s[nt].y;
                int gc = ktb + nt * 8 + 2 * t;
                sv[2*nt]   = (gc     <= gr) ? x0 * 0.125f : -1e30f;
                sv[2*nt+1] = (gc + 1 <= gr) ? x1 * 0.125f : -1e30f;
                cm = fmaxf(cm, fmaxf(sv[2*nt], sv[2*nt+1]));
            }
            cm = fmaxf(cm, __shfl_xor_sync(0xffffffffu, cm, 1));
            cm = fmaxf(cm, __shfl_xor_sync(0xffffffffu, cm, 2));
            if (cm > -1e29f) {
                float mn = fmaxf(mr[rr], cm), se = 0.f, st = 0.f;
#pragma unroll
                for (int i = 0; i < 16; i++) {
                    float e = __expf(sv[i] - mn);
                    se += e; st = fmaf(e, sv[i], st);
                }
                se += __shfl_xor_sync(0xffffffffu, se, 1);
                se += __shfl_xor_sync(0xffffffffu, se, 2);
                st += __shfl_xor_sync(0xffffffffu, st, 1);
                st += __shfl_xor_sync(0xffffffffu, st, 2);
                float corr = __expf(mr[rr] - mn);
                lr[rr] = fmaf(lr[rr], corr, se);
                tr[rr] = fmaf(tr[rr], corr, st);
                mr[rr] = mn;
            }
        }
    }

    float bs[2], bm[2], l2[2] = {0.f, 0.f};
#pragma unroll
    for (int rr = 0; rr < 2; rr++) {
        float ent = logf(lr[rr]) + mr[rr] - tr[rr] / lr[rr];
        float beta = 1.f;
        if (ent > 0.5f) {
            float poly = ((((-0.037f * ent + 0.481f) * ent - 2.3f) * ent + 4.917f) * ent - 1.791f);
            beta = fmaxf(poly, 1.f);
        }
        bs[rr] = beta * 0.125f;
        bm[rr] = beta * mr[rr];
    }

    float4 o[8];
#pragma unroll
    for (int nt = 0; nt < 8; nt++) o[nt] = make_float4(0.f, 0.f, 0.f, 0.f);

    // ================= pass B =================
    for (int kt = 0; kt <= ktmax; kt++) {
        int ktb = kt * 64;
        __syncthreads();
#pragma unroll
        for (int i = 0; i < 4; i++) {
            int idx = tid + i * 256, r = idx >> 4, c4 = idx & 15;
            float4 vk = *(const float4*)&K[(size_t)(ktb + r) * HD + c4 * 4];
            float4 vv = *(const float4*)&V[(size_t)(ktb + r) * HD + c4 * 4];
            float2* pk = &Ks[r * AST + c4 * 4];
            float2* pv = &Vs[r * AST + c4 * 4];
            pk[0] = tsplit(vk.x); pk[1] = tsplit(vk.y); pk[2] = tsplit(vk.z); pk[3] = tsplit(vk.w);
            pv[0] = tsplit(vv.x); pv[1] = tsplit(vv.y); pv[2] = tsplit(vv.z); pv[3] = tsplit(vv.w);
        }
        __syncthreads();
        if (ktb > q0 + wr + 15) continue;

        float4 s[8];
#pragma unroll
        for (int nt = 0; nt < 8; nt++) s[nt] = make_float4(0.f, 0.f, 0.f, 0.f);
#pragma unroll
        for (int kk = 0; kk < 8; kk++) {
            float2 af[4];
            af[0] = Qs[(wr + g)     * AST + kk * 8 + t];
            af[1] = Qs[(wr + g + 8) * AST + kk * 8 + t];
            af[2] = Qs[(wr + g)     * AST + kk * 8 + t + 4];
            af[3] = Qs[(wr + g + 8) * AST + kk * 8 + t + 4];
#pragma unroll
            for (int nt = 0; nt < 8; nt++) {
                float2 bf[2];
                bf[0] = Ks[(nt * 8 + g) * AST + kk * 8 + t];
                bf[1] = Ks[(nt * 8 + g) * AST + kk * 8 + t + 4];
                mma3(s[nt], af, bf);
            }
        }
        // P = exp(beta*s - beta*m), store split into warp-private Ps rows
#pragma unroll
        for (int rr = 0; rr < 2; rr++) {
            int gr = rr ? gr1 : gr0;
            int prow = wr + g + rr * 8;
#pragma unroll
            for (int nt = 0; nt < 8; nt++) {
                float x0 = rr ? s[nt].z : s[nt].x;
                float x1 = rr ? s[nt].w : s[nt].y;
                int gc = ktb + nt * 8 + 2 * t;
                float p0 = (gc     <= gr) ? __expf(fmaf(bs[rr], x0, -bm[rr])) : 0.f;
                float p1 = (gc + 1 <= gr) ? __expf(fmaf(bs[rr], x1, -bm[rr])) : 0.f;
                l2[rr] += p0 + p1;
                float2 s0 = tsplit(p0), s1 = tsplit(p1);
                float4 w4 = make_float4(s0.x, s0.y, s1.x, s1.y);
                *(float4*)&Ps[prow * AST + nt * 8 + 2 * t] = w4;
            }
        }
        __syncwarp();
        // O += P * V
#pragma unroll
        for (int kk = 0; kk < 8; kk++) {
            float2 af[4];
            af[0] = Ps[(wr + g)     * AST + kk * 8 + t];
            af[1] = Ps[(wr + g + 8) * AST + kk * 8 + t];
            af[2] = Ps[(wr + g)     * AST + kk * 8 + t + 4];
            af[3] = Ps[(wr + g + 8) * AST + kk * 8 + t + 4];
#pragma unroll
            for (int nt = 0; nt < 8; nt++) {
                float2 bf[2];
                bf[0] = Vs[(kk * 8 + t)     * AST + nt * 8 + g];
                bf[1] = Vs[(kk * 8 + t + 4) * AST + nt * 8 + g];
                mma3(o[nt], af, bf);
            }
        }
        __syncwarp();
    }

#pragma unroll
    for (int rr = 0; rr < 2; rr++) {
        l2[rr] += __shfl_xor_sync(0xffffffffu, l2[rr], 1);
        l2[rr] += __shfl_xor_sync(0xffffffffu, l2[rr], 2);
    }
    float inv0 = 1.f / l2[0], inv1 = 1.f / l2[1];
    size_t row0 = ((size_t)(b * NN) + gr0) * DD + h * HD;
    size_t row1 = ((size_t)(b * NN) + gr1) * DD + h * HD;
#pragma unroll
    for (int nt = 0; nt < 8; nt++) {
        int c = nt * 8 + 2 * t;
        *(float2*)&gctx[row0 + c] = make_float2(o[nt].x * inv0, o[nt].y * inv0);
        *(float2*)&gctx[row1 + c] = make_float2(o[nt].z * inv1, o[nt].w * inv1);
    }
}

// ============================================================
extern "C" void kernel_launch(void* const* d_in, const int* in_sizes, int n_in,
                              void* d_out, int out_size)
{
    const float* x  = (const float*)d_in[0];
    const float* Wq = (const float*)d_in[1];
    const float* Wk = (const float*)d_in[2];
    const float* Wv = (const float*)d_in[3];
    const float* Wo = (const float*)d_in[4];
    const float* bo = (const float*)d_in[5];
    float* out = (float*)d_out;

    float *qp, *kp, *vp, *ctxp;
    cudaGetSymbolAddress((void**)&qp,   g_q);
    cudaGetSymbolAddress((void**)&kp,   g_k);
    cudaGetSymbolAddress((void**)&vp,   g_v);
    cudaGetSymbolAddress((void**)&ctxp, g_ctx);

    const int gsmem = 2 * 128 * GST * (int)sizeof(float2);   // 73728
    const int asmem = 384 * AST * (int)sizeof(float2);       // 208896
    cudaFuncSetAttribute(gemm_mma, cudaFuncAttributeMaxDynamicSharedMemorySize, gsmem);
    cudaFuncSetAttribute(attn_mma, cudaFuncAttributeMaxDynamicSharedMemorySize, asmem);

    dim3 gg(DD / 128, (BB * NN) / 128);    // (8, 32)
    gemm_mma<<<gg, 256, gsmem>>>(x, Wq, nullptr, qp, 0);
    gemm_mma<<<gg, 256, gsmem>>>(x, Wk, nullptr, kp, 0);
    gemm_mma<<<gg, 256, gsmem>>>(x, Wv, nullptr, vp, 0);

    dim3 ag(NN / 128, HH, BB);             // (16, 16, 2)
    attn_mma<<<ag, 256, asmem>>>(ctxp);

    gemm_mma<<<gg, 256, gsmem>>>(ctxp, Wo, bo, out, 1);
}

// round 5
// speedup vs baseline: 1.9590x; 1.1125x over previous
#include <cuda_runtime.h>
#include <cstdint>
#include <math.h>

#define BB 2
#define NN 2048
#define DD 1024
#define HH 16
#define HD 64

__device__ float g_q[(size_t)BB*HH*NN*HD];
__device__ float g_k[(size_t)BB*HH*NN*HD];
__device__ float g_v[(size_t)BB*HH*NN*HD];
__device__ float g_ctx[(size_t)BB*NN*DD];
// S cache: 512 blocks (b,h,qtile) x 32 key-tiles x 8192 floats (packed per-thread)
__device__ float g_s[(size_t)512*262144];

__device__ __forceinline__ float tf32r(float x){
    uint32_t r; asm("cvt.rna.tf32.f32 %0, %1;" : "=r"(r) : "f"(x));
    return __uint_as_float(r);
}
__device__ __forceinline__ float2 tsplit(float x){
    float h = tf32r(x);
    return make_float2(h, tf32r(x - h));
}
__device__ __forceinline__ void mma1(float4& d, uint32_t a0, uint32_t a1, uint32_t a2, uint32_t a3,
                                     uint32_t b0, uint32_t b1){
    asm volatile("mma.sync.aligned.m16n8k8.row.col.f32.tf32.tf32.f32 "
        "{%0,%1,%2,%3},{%4,%5,%6,%7},{%8,%9},{%0,%1,%2,%3};"
        : "+f"(d.x), "+f"(d.y), "+f"(d.z), "+f"(d.w)
        : "r"(a0), "r"(a1), "r"(a2), "r"(a3), "r"(b0), "r"(b1));
}
#define FU __float_as_uint
__device__ __forceinline__ void mma3(float4& d, const float2* a, const float2* b){
    mma1(d, FU(a[0].x), FU(a[1].x), FU(a[2].x), FU(a[3].x), FU(b[0].x), FU(b[1].x));
    mma1(d, FU(a[0].x), FU(a[1].x), FU(a[2].x), FU(a[3].x), FU(b[0].y), FU(b[1].y));
    mma1(d, FU(a[0].y), FU(a[1].y), FU(a[2].y), FU(a[3].y), FU(b[0].x), FU(b[1].x));
}

// ============================================================
// GEMM core: 128x128 tile, BK=32, double-buffered, reg prefetch.
// ============================================================
#define GST 36

__device__ __forceinline__ void g_ld(const float* __restrict__ A, const float* __restrict__ W,
                                     int m0, int n0, int k0, int tid, float4* va, float4* vb){
#pragma unroll
    for (int i = 0; i < 4; i++) {
        int idx = tid + i * 256, r = idx >> 3, c4 = idx & 7;
        va[i] = *(const float4*)&A[(size_t)(m0 + r) * DD + k0 + c4 * 4];
        vb[i] = *(const float4*)&W[(size_t)(n0 + r) * DD + k0 + c4 * 4];
    }
}
__device__ __forceinline__ void g_st(float2* As, float2* Bs, int tid, const float4* va, const float4* vb){
#pragma unroll
    for (int i = 0; i < 4; i++) {
        int idx = tid + i * 256, r = idx >> 3, c4 = idx & 7;
        float2* pa = &As[r * GST + c4 * 4];
        float2* pb = &Bs[r * GST + c4 * 4];
        pa[0] = tsplit(va[i].x); pa[1] = tsplit(va[i].y);
        pa[2] = tsplit(va[i].z); pa[3] = tsplit(va[i].w);
        pb[0] = tsplit(vb[i].x); pb[1] = tsplit(vb[i].y);
        pb[2] = tsplit(vb[i].z); pb[3] = tsplit(vb[i].w);
    }
}
__device__ __forceinline__ void g_mma(const float2* As, const float2* Bs, float4 (&acc)[2][8],
                                      int wm, int wn, int g, int t){
#pragma unroll
    for (int kk = 0; kk < 4; kk++) {
        float2 af[2][4];
#pragma unroll
        for (int mt = 0; mt < 2; mt++) {
            int rb = wm * 32 + mt * 16;
            af[mt][0] = As[(rb + g)     * GST + kk * 8 + t];
            af[mt][1] = As[(rb + g + 8) * GST + kk * 8 + t];
            af[mt][2] = As[(rb + g)     * GST + kk * 8 + t + 4];
            af[mt][3] = As[(rb + g + 8) * GST + kk * 8 + t + 4];
        }
#pragma unroll
        for (int nt = 0; nt < 8; nt++) {
            int nr = wn * 64 + nt * 8 + g;
            float2 bf[2];
            bf[0] = Bs[nr * GST + kk * 8 + t];
            bf[1] = Bs[nr * GST + kk * 8 + t + 4];
            mma3(acc[0][nt], af[0], bf);
            mma3(acc[1][nt], af[1], bf);
        }
    }
}
__device__ __forceinline__ void g_run(const float* __restrict__ A, const float* __restrict__ W,
                                      float2* sm, int m0, int n0, int tid,
                                      float4 (&acc)[2][8], int wm, int wn, int g, int t){
    float2* As0 = sm;
    float2* Bs0 = As0 + 128 * GST;
    float2* As1 = Bs0 + 128 * GST;
    float2* Bs1 = As1 + 128 * GST;
    float4 va[4], vb[4];
    g_ld(A, W, m0, n0, 0, tid, va, vb);
    for (int k0 = 0; k0 < DD; k0 += 32) {
        float2* As = (k0 & 32) ? As1 : As0;
        float2* Bs = (k0 & 32) ? Bs1 : Bs0;
        g_st(As, Bs, tid, va, vb);
        __syncthreads();
        if (k0 + 32 < DD) g_ld(A, W, m0, n0, k0 + 32, tid, va, vb);
        g_mma(As, Bs, acc, wm, wn, g, t);
    }
}

// fused QKV: grid.x = 3 mats * 8 n-tiles, grid.y = 32 m-tiles
__global__ __launch_bounds__(256) void gemm_qkv(
    const float* __restrict__ x,
    const float* __restrict__ Wq, const float* __restrict__ Wk, const float* __restrict__ Wv,
    float* __restrict__ qp, float* __restrict__ kp, float* __restrict__ vp)
{
    extern __shared__ float2 gsm[];
    const int tid = threadIdx.x, lane = tid & 31, wid = tid >> 5;
    const int g = lane >> 2, t = lane & 3;
    const int wm = wid >> 1, wn = wid & 1;
    const int mat = blockIdx.x >> 3;
    const int m0 = blockIdx.y * 128, n0 = (blockIdx.x & 7) * 128;
    const float* W = (mat == 0) ? Wq : (mat == 1) ? Wk : Wv;
    float* C = (mat == 0) ? qp : (mat == 1) ? kp : vp;

    float4 acc[2][8];
#pragma unroll
    for (int i = 0; i < 2; i++)
#pragma unroll
        for (int j = 0; j < 8; j++) acc[i][j] = make_float4(0.f, 0.f, 0.f, 0.f);

    g_run(x, W, gsm, m0, n0, tid, acc, wm, wn, g, t);

#pragma unroll
    for (int mt = 0; mt < 2; mt++) {
        int r0 = m0 + wm * 32 + mt * 16 + g;
#pragma unroll
        for (int nt = 0; nt < 8; nt++) {
            int n = n0 + wn * 64 + nt * 8 + 2 * t;
            int h = n >> 6, cc = n & 63;
            float4 c = acc[mt][nt];
            int b0r = r0 >> 11, i0r = r0 & (NN - 1);
            int b1r = (r0 + 8) >> 11, i1r = (r0 + 8) & (NN - 1);
            *(float2*)&C[((size_t)(b0r * HH + h) * NN + i0r) * HD + cc] = make_float2(c.x, c.y);
            *(float2*)&C[((size_t)(b1r * HH + h) * NN + i1r) * HD + cc] = make_float2(c.z, c.w);
        }
    }
}

__global__ __launch_bounds__(256) void gemm_out(
    const float* __restrict__ A, const float* __restrict__ W,
    const float* __restrict__ bias, float* __restrict__ C)
{
    extern __shared__ float2 gsm[];
    const int tid = threadIdx.x, lane = tid & 31, wid = tid >> 5;
    const int g = lane >> 2, t = lane & 3;
    const int wm = wid >> 1, wn = wid & 1;
    const int m0 = blockIdx.y * 128, n0 = blockIdx.x * 128;

    float4 acc[2][8];
#pragma unroll
    for (int i = 0; i < 2; i++)
#pragma unroll
        for (int j = 0; j < 8; j++) acc[i][j] = make_float4(0.f, 0.f, 0.f, 0.f);

    g_run(A, W, gsm, m0, n0, tid, acc, wm, wn, g, t);

#pragma unroll
    for (int mt = 0; mt < 2; mt++) {
        int r0 = m0 + wm * 32 + mt * 16 + g;
#pragma unroll
        for (int nt = 0; nt < 8; nt++) {
            int n = n0 + wn * 64 + nt * 8 + 2 * t;
            float bx = bias[n], by = bias[n + 1];
            float4 c = acc[mt][nt];
            *(float2*)&C[(size_t)r0 * DD + n]       = make_float2(c.x + bx, c.y + by);
            *(float2*)&C[(size_t)(r0 + 8) * DD + n] = make_float2(c.z + bx, c.w + by);
        }
    }
}

// ============================================================
// Attention: 256 thr, q-tile 128, key-tile 64, S cached in gmem.
// ============================================================
#define AST 68

__global__ __launch_bounds__(256, 2) void attn_mma(float* __restrict__ gctx)
{
    extern __shared__ float2 asm_[];
    // pass A: Qs[128*AST], Ks[64*AST];  pass B aliases: Ps[128*AST], Vs[64*AST]
    float2* Qs = asm_;
    float2* Ks = asm_ + 128 * AST;
    float2* Ps = asm_;
    float2* Vs = asm_ + 128 * AST;

    const int tid = threadIdx.x, lane = tid & 31, wid = tid >> 5;
    const int g = lane >> 2, t = lane & 3;
    const int qt = 15 - blockIdx.x;
    const int h = blockIdx.y, b = blockIdx.z;
    const int q0 = qt * 128, ktmax = 2 * qt + 1;
    const size_t ho = (size_t)(b * HH + h) * NN * HD;
    const float *Q = g_q + ho, *K = g_k + ho, *V = g_v + ho;
    float* Sc = g_s + (size_t)((b * HH + h) * 16 + qt) * 262144 + wid * 1024 + lane * 2;

    const int wr = wid * 16;
    const int gr0 = q0 + wr + g, gr1 = gr0 + 8;

#pragma unroll
    for (int i = 0; i < 8; i++) {
        int idx = tid + i * 256, r = idx >> 4, c4 = idx & 15;
        float4 v = *(const float4*)&Q[(size_t)(q0 + r) * HD + c4 * 4];
        float2* p = &Qs[r * AST + c4 * 4];
        p[0] = tsplit(v.x); p[1] = tsplit(v.y); p[2] = tsplit(v.z); p[3] = tsplit(v.w);
    }

    float mr[2] = {-1e30f, -1e30f}, lr[2] = {0.f, 0.f}, tr[2] = {0.f, 0.f};

    // ================= pass A: stats + store S =================
    for (int kt = 0; kt <= ktmax; kt++) {
        int ktb = kt * 64;
        __syncthreads();
#pragma unroll
        for (int i = 0; i < 4; i++) {
            int idx = tid + i * 256, r = idx >> 4, c4 = idx & 15;
            float4 v = *(const float4*)&K[(size_t)(ktb + r) * HD + c4 * 4];
            float2* p = &Ks[r * AST + c4 * 4];
            p[0] = tsplit(v.x); p[1] = tsplit(v.y); p[2] = tsplit(v.z); p[3] = tsplit(v.w);
        }
        __syncthreads();
        if (ktb > q0 + wr + 15) continue;

        float4 s[8];
#pragma unroll
        for (int nt = 0; nt < 8; nt++) s[nt] = make_float4(0.f, 0.f, 0.f, 0.f);
#pragma unroll
        for (int kk = 0; kk < 8; kk++) {
            float2 af[4];
            af[0] = Qs[(wr + g)     * AST + kk * 8 + t];
            af[1] = Qs[(wr + g + 8) * AST + kk * 8 + t];
            af[2] = Qs[(wr + g)     * AST + kk * 8 + t + 4];
            af[3] = Qs[(wr + g + 8) * AST + kk * 8 + t + 4];
#pragma unroll
            for (int nt = 0; nt < 8; nt++) {
                float2 bf[2];
                bf[0] = Ks[(nt * 8 + g) * AST + kk * 8 + t];
                bf[1] = Ks[(nt * 8 + g) * AST + kk * 8 + t + 4];
                mma3(s[nt], af, bf);
            }
        }
        float* sp = Sc + kt * 8192;
#pragma unroll
        for (int rr = 0; rr < 2; rr++) {
            int gr = rr ? gr1 : gr0;
            float sv[16], cm = -1e30f;
#pragma unroll
            for (int nt = 0; nt < 8; nt++) {
                float x0 = rr ? s[nt].z : s[nt].x;
                float x1 = rr ? s[nt].w : s[nt].y;
                int gc = ktb + nt * 8 + 2 * t;
                sv[2*nt]   = (gc     <= gr) ? x0 * 0.125f : -1e30f;
                sv[2*nt+1] = (gc + 1 <= gr) ? x1 * 0.125f : -1e30f;
                cm = fmaxf(cm, fmaxf(sv[2*nt], sv[2*nt+1]));
                *(float2*)&sp[(rr * 8 + nt) * 64] = make_float2(sv[2*nt], sv[2*nt+1]);
            }
            cm = fmaxf(cm, __shfl_xor_sync(0xffffffffu, cm, 1));
            cm = fmaxf(cm, __shfl_xor_sync(0xffffffffu, cm, 2));
            if (cm > -1e29f) {
                float mn = fmaxf(mr[rr], cm), se = 0.f, st = 0.f;
#pragma unroll
                for (int i = 0; i < 16; i++) {
                    float e = __expf(sv[i] - mn);
                    se += e; st = fmaf(e, sv[i], st);
                }
                se += __shfl_xor_sync(0xffffffffu, se, 1);
                se += __shfl_xor_sync(0xffffffffu, se, 2);
                st += __shfl_xor_sync(0xffffffffu, st, 1);
                st += __shfl_xor_sync(0xffffffffu, st, 2);
                float corr = __expf(mr[rr] - mn);
                lr[rr] = fmaf(lr[rr], corr, se);
                tr[rr] = fmaf(tr[rr], corr, st);
                mr[rr] = mn;
            }
        }
    }

    float bs[2], bm[2], l2[2] = {0.f, 0.f};
#pragma unroll
    for (int rr = 0; rr < 2; rr++) {
        float ent = logf(lr[rr]) + mr[rr] - tr[rr] / lr[rr];
        float beta = 1.f;
        if (ent > 0.5f) {
            float poly = ((((-0.037f * ent + 0.481f) * ent - 2.3f) * ent + 4.917f) * ent - 1.791f);
            beta = fmaxf(poly, 1.f);
        }
        bs[rr] = beta;
        bm[rr] = beta * mr[rr];
    }

    float4 o[8];
#pragma unroll
    for (int nt = 0; nt < 8; nt++) o[nt] = make_float4(0.f, 0.f, 0.f, 0.f);

    // ================= pass B: P = exp(beta*S - beta*m), O += P V =================
    for (int kt = 0; kt <= ktmax; kt++) {
        int ktb = kt * 64;
        __syncthreads();
#pragma unroll
        for (int i = 0; i < 4; i++) {
            int idx = tid + i * 256, r = idx >> 4, c4 = idx & 15;
            float4 vv = *(const float4*)&V[(size_t)(ktb + r) * HD + c4 * 4];
            float2* pv = &Vs[r * AST + c4 * 4];
            pv[0] = tsplit(vv.x); pv[1] = tsplit(vv.y); pv[2] = tsplit(vv.z); pv[3] = tsplit(vv.w);
        }
        __syncthreads();
        if (ktb > q0 + wr + 15) continue;

        const float* sp = Sc + kt * 8192;
#pragma unroll
        for (int rr = 0; rr < 2; rr++) {
            int prow = wr + g + rr * 8;
#pragma unroll
            for (int nt = 0; nt < 8; nt++) {
                float2 sv2 = *(const float2*)&sp[(rr * 8 + nt) * 64];
                float p0 = __expf(fmaf(bs[rr], sv2.x, -bm[rr]));
                float p1 = __expf(fmaf(bs[rr], sv2.y, -bm[rr]));
                l2[rr] += p0 + p1;
                float2 s0 = tsplit(p0), s1 = tsplit(p1);
                *(float4*)&Ps[prow * AST + nt * 8 + 2 * t] = make_float4(s0.x, s0.y, s1.x, s1.y);
            }
        }
        __syncwarp();
#pragma unroll
        for (int kk = 0; kk < 8; kk++) {
            float2 af[4];
            af[0] = Ps[(wr + g)     * AST + kk * 8 + t];
            af[1] = Ps[(wr + g + 8) * AST + kk * 8 + t];
            af[2] = Ps[(wr + g)     * AST + kk * 8 + t + 4];
            af[3] = Ps[(wr + g + 8) * AST + kk * 8 + t + 4];
#pragma unroll
            for (int nt = 0; nt < 8; nt++) {
                float2 bf[2];
                bf[0] = Vs[(kk * 8 + t)     * AST + nt * 8 + g];
                bf[1] = Vs[(kk * 8 + t + 4) * AST + nt * 8 + g];
                mma3(o[nt], af, bf);
            }
        }
        __syncwarp();
    }

#pragma unroll
    for (int rr = 0; rr < 2; rr++) {
        l2[rr] += __shfl_xor_sync(0xffffffffu, l2[rr], 1);
        l2[rr] += __shfl_xor_sync(0xffffffffu, l2[rr], 2);
    }
    float inv0 = 1.f / l2[0], inv1 = 1.f / l2[1];
    size_t row0 = ((size_t)(b * NN) + gr0) * DD + h * HD;
    size_t row1 = ((size_t)(b * NN) + gr1) * DD + h * HD;
#pragma unroll
    for (int nt = 0; nt < 8; nt++) {
        int c = nt * 8 + 2 * t;
        *(float2*)&gctx[row0 + c] = make_float2(o[nt].x * inv0, o[nt].y * inv0);
        *(float2*)&gctx[row1 + c] = make_float2(o[nt].z * inv1, o[nt].w * inv1);
    }
}

// ============================================================
extern "C" void kernel_launch(void* const* d_in, const int* in_sizes, int n_in,
                              void* d_out, int out_size)
{
    const float* x  = (const float*)d_in[0];
    const float* Wq = (const float*)d_in[1];
    const float* Wk = (const float*)d_in[2];
    const float* Wv = (const float*)d_in[3];
    const float* Wo = (const float*)d_in[4];
    const float* bo = (const float*)d_in[5];
    float* out = (float*)d_out;

    float *qp, *kp, *vp, *ctxp;
    cudaGetSymbolAddress((void**)&qp,   g_q);
    cudaGetSymbolAddress((void**)&kp,   g_k);
    cudaGetSymbolAddress((void**)&vp,   g_v);
    cudaGetSymbolAddress((void**)&ctxp, g_ctx);

    const int gsmem = 4 * 128 * GST * (int)sizeof(float2);   // 147456
    const int asmem = 192 * AST * (int)sizeof(float2);       // 104448
    cudaFuncSetAttribute(gemm_qkv, cudaFuncAttributeMaxDynamicSharedMemorySize, gsmem);
    cudaFuncSetAttribute(gemm_out, cudaFuncAttributeMaxDynamicSharedMemorySize, gsmem);
    cudaFuncSetAttribute(attn_mma, cudaFuncAttributeMaxDynamicSharedMemorySize, asmem);

    dim3 qg(24, 32);
    gemm_qkv<<<qg, 256, gsmem>>>(x, Wq, Wk, Wv, qp, kp, vp);

    dim3 ag(NN / 128, HH, BB);
    attn_mma<<<ag, 256, asmem>>>(ctxp);

    dim3 og(8, 32);
    gemm_out<<<og, 256, gsmem>>>(ctxp, Wo, bo, out);
}